// round 10
// baseline (speedup 1.0000x reference)
#include <cuda_runtime.h>
#include <cstdint>

#define NWORDS  16384
#define LW      32
#define NC      64
#define E3      256
#define OUTW    770
#define NW_BLK  64           // words per block
#define GRID    256          // 16384 / 64
#define BLOCKT  256

#define TABROW   260         // floats per char row (pad: CF gather, 4-way fill)
#define TABROWB  1040u
#define CNTROW   66          // f32x2 per count row; 528 B stride (16B-aligned!)
#define TAB_OFF  0           // fp32 table [64 chars][260] = 66560 B
#define CNT_OFF  66560       // f32x2 counts [64 chars][66] = 33792 B
#define META_OFF 100352      // u32 [64 words][2] = 512 B
#define SMEM_TOTAL 100864

typedef unsigned long long ull;

__device__ __forceinline__ void lds128(uint32_t a, ull &x, ull &y) {
    asm("ld.shared.v2.b64 {%0,%1}, [%2];" : "=l"(x), "=l"(y) : "r"(a));
}
__device__ __forceinline__ void fma2(ull &acc, ull c, ull b) {
    asm("fma.rn.f32x2 %0, %1, %2, %0;" : "+l"(acc) : "l"(c), "l"(b));
}
__device__ __forceinline__ ull packf(float v) {
    ull r; uint32_t u = __float_as_uint(v);
    asm("mov.b64 %0, {%1, %1};" : "=l"(r) : "r"(u)); return r;
}

__global__ __launch_bounds__(BLOCKT, 2) void opb_kernel(
    const int* __restrict__ sntcs, const float* __restrict__ W,
    float* __restrict__ out)
{
    extern __shared__ char smem[];
    uint32_t sb;
    asm("{ .reg .u64 t; cvta.to.shared.u64 t, %1; cvt.u32.u64 %0, t; }" : "=r"(sb) : "l"(smem));
    float*    sTab  = (float*)(smem + TAB_OFF);
    uint32_t* sMeta = (uint32_t*)(smem + META_OFF);

    const int tid  = threadIdx.x;
    const int lane = tid & 31;
    const int wg   = tid >> 5;               // warp owns words wg*8..wg*8+7
    const int wbase = blockIdx.x * NW_BLK;

    // ---- prologue: chars for this warp's 8 words (overlap with fill) ----
    int ch[8];
    #pragma unroll
    for (int t = 0; t < 8; t++)
        ch[t] = sntcs[(size_t)(wbase + wg * 8 + t) * LW + lane];

    // ---- fill fp32 table: sTab[c][d] = W[d*64+c] (LDG coalesced) ----
    for (int idx = tid; idx < E3 * NC; idx += BLOCKT) {
        int d = idx >> 6, c = idx & 63;
        sTab[c * TABROW + d] = W[idx];
    }

    // ---- metadata + counts (warp-local, 8 words) ----
    #pragma unroll
    for (int t = 0; t < 8; t++) {
        int c = ch[t];
        unsigned key = ((unsigned)c << 5) | (unsigned)(31 - lane);
        #pragma unroll
        for (int off = 16; off; off >>= 1) {
            unsigned o = __shfl_xor_sync(0xffffffffu, key, off);
            key = key > o ? key : o;
        }
        int p  = 31 - (int)(key & 31u);                 // first-occurrence argmax
        int wl = p - 1; if (wl < 0) wl = 0;             // relu(argmax-1)
        int ends = __shfl_sync(0xffffffffu, c, wl);     // gather BEFORE scatter
        int s = (lane == wl) ? 0 : c;                   // scatter 0 at wl
        if (lane == 31) s = ends;                       // last := ends
        int fc = __shfl_sync(0xffffffffu, s, 0);        // first char (post-edit)
        int cnt0 = 0, cnt1 = 0;                         // counts, interior 1..30
        #pragma unroll
        for (int l = 1; l <= 30; l++) {
            int sl = __shfl_sync(0xffffffffu, s, l);
            cnt0 += (sl == lane);
            cnt1 += (sl == lane + 32);
        }
        const int w = wg * 8 + t;
        // packed {cnt,cnt} f32x2 at [char][word]; 528B row stride, 16B-aligned
        ull p0 = packf((float)cnt0), p1 = packf((float)cnt1);
        asm volatile("st.shared.b64 [%0], %1;" ::
            "r"(sb + CNT_OFF + (uint32_t)(lane * CNTROW + w) * 8u), "l"(p0) : "memory");
        asm volatile("st.shared.b64 [%0], %1;" ::
            "r"(sb + CNT_OFF + (uint32_t)((lane + 32) * CNTROW + w) * 8u), "l"(p1) : "memory");
        if (lane == 0) {
            sMeta[w * 2]     = (uint32_t)fc * TABROWB;
            sMeta[w * 2 + 1] = (uint32_t)ends * TABROWB;
        }
    }
    __syncthreads();

    // ---- GEMM: bow[w][d] = sum_c cnt[w][c] * Wt[c][d], f32x2 tiles ----
    // thread tile: 8 words (wg*8..+7) x 8 dims (lane*4..+3 and 128+lane*4..+3)
    ull acc[8][4];
    #pragma unroll
    for (int w = 0; w < 8; w++)
        #pragma unroll
        for (int j = 0; j < 4; j++) acc[w][j] = 0ull;

    uint32_t tb = sb + TAB_OFF + (uint32_t)lane * 16u;
    uint32_t cb = sb + CNT_OFF + (uint32_t)wg * 64u;    // word w0=wg*8 -> byte 8*w0

    #pragma unroll 4
    for (int k = 0; k < NC; k++) {
        ull b0, b1, b2, b3;
        lds128(tb, b0, b1);                 // dims lane*4..+3      (CF)
        lds128(tb + 512u, b2, b3);          // dims 128+lane*4..+3  (CF)
        ull c0,c1,c2,c3,c4,c5,c6,c7;        // 8 words' packed counts (broadcast)
        lds128(cb,        c0, c1);
        lds128(cb + 16u,  c2, c3);
        lds128(cb + 32u,  c4, c5);
        lds128(cb + 48u,  c6, c7);
        fma2(acc[0][0], c0, b0); fma2(acc[0][1], c0, b1); fma2(acc[0][2], c0, b2); fma2(acc[0][3], c0, b3);
        fma2(acc[1][0], c1, b0); fma2(acc[1][1], c1, b1); fma2(acc[1][2], c1, b2); fma2(acc[1][3], c1, b3);
        fma2(acc[2][0], c2, b0); fma2(acc[2][1], c2, b1); fma2(acc[2][2], c2, b2); fma2(acc[2][3], c2, b3);
        fma2(acc[3][0], c3, b0); fma2(acc[3][1], c3, b1); fma2(acc[3][2], c3, b2); fma2(acc[3][3], c3, b3);
        fma2(acc[4][0], c4, b0); fma2(acc[4][1], c4, b1); fma2(acc[4][2], c4, b2); fma2(acc[4][3], c4, b3);
        fma2(acc[5][0], c5, b0); fma2(acc[5][1], c5, b1); fma2(acc[5][2], c5, b2); fma2(acc[5][3], c5, b3);
        fma2(acc[6][0], c6, b0); fma2(acc[6][1], c6, b1); fma2(acc[6][2], c6, b2); fma2(acc[6][3], c6, b3);
        fma2(acc[7][0], c7, b0); fma2(acc[7][1], c7, b1); fma2(acc[7][2], c7, b2); fma2(acc[7][3], c7, b3);
        tb += TABROWB;
        cb += CNTROW * 8u;                  // 528 B: stays 16B-aligned
    }

    // ---- epilogue: bow stores + first/last gathers + pad ----
    #pragma unroll
    for (int w = 0; w < 8; w++) {
        const int gw = wbase + wg * 8 + w;
        float* o = out + (size_t)gw * OUTW;
        const int d4 = lane * 4;
        // bow segment (base 2+E3 = 258)
        *(ull*)(o + 258 + d4)       = acc[w][0];
        *(ull*)(o + 260 + d4)       = acc[w][1];
        *(ull*)(o + 258 + 128 + d4) = acc[w][2];
        *(ull*)(o + 260 + 128 + d4) = acc[w][3];
        // first / last from table (conflict-free, uniform row)
        const uint32_t fo = sMeta[(wg * 8 + w) * 2];
        const uint32_t lo = sMeta[(wg * 8 + w) * 2 + 1];
        const uint32_t la = (uint32_t)lane * 16u;
        ull x, y;
        lds128(sb + TAB_OFF + fo + la, x, y);
        *(ull*)(o + 2 + d4)   = x;  *(ull*)(o + 4 + d4)   = y;
        lds128(sb + TAB_OFF + fo + 512u + la, x, y);
        *(ull*)(o + 130 + d4) = x;  *(ull*)(o + 132 + d4) = y;
        lds128(sb + TAB_OFF + lo + la, x, y);
        *(ull*)(o + 514 + d4) = x;  *(ull*)(o + 516 + d4) = y;
        lds128(sb + TAB_OFF + lo + 512u + la, x, y);
        *(ull*)(o + 642 + d4) = x;  *(ull*)(o + 644 + d4) = y;
        if (lane == 0) *(ull*)o = 0ull;                 // left zero pad
    }
}

extern "C" void kernel_launch(void* const* d_in, const int* in_sizes, int n_in,
                              void* d_out, int out_size)
{
    const int*   sntcs = (const int*)d_in[0];
    const float* W     = (const float*)d_in[1];
    float*       out   = (float*)d_out;

    cudaFuncSetAttribute(opb_kernel, cudaFuncAttributeMaxDynamicSharedMemorySize, SMEM_TOTAL);
    opb_kernel<<<GRID, BLOCKT, SMEM_TOTAL>>>(sntcs, W, out);
}

// round 11
// speedup vs baseline: 1.0752x; 1.0752x over previous
#include <cuda_runtime.h>
#include <cstdint>

#define NWORDS  16384
#define LW      32
#define NC      64
#define E3      256
#define OUTW    770
#define NW_BLK  32           // words per block
#define GRID    512          // 16384 / 32
#define BLOCKT  256

#define TABROW   260         // floats per char row (1040 B: 16B-aligned, CF gather)
#define TABROWB  1040u
#define CNTROW   36          // f32 per count row (144 B: 16B-aligned walk)
#define TAB_OFF  0           // fp32 table [64][260] = 66560 B
#define CNT_OFF  66560       // f32 counts [64][36]  = 9216 B
#define META_OFF 75776       // u32 [32 words][2]    = 256 B
#define SMEM_TOTAL 76032

typedef unsigned long long ull;

__device__ __forceinline__ void lds128(uint32_t a, ull &x, ull &y) {
    asm("ld.shared.v2.b64 {%0,%1}, [%2];" : "=l"(x), "=l"(y) : "r"(a));
}
__device__ __forceinline__ void fma2(ull &acc, ull c, ull b) {
    asm("fma.rn.f32x2 %0, %1, %2, %0;" : "+l"(acc) : "l"(c), "l"(b));
}
__device__ __forceinline__ ull pk(uint32_t u) {
    ull r; asm("mov.b64 %0, {%1, %1};" : "=l"(r) : "r"(u)); return r;
}

__global__ __launch_bounds__(BLOCKT, 3) void opb_kernel(
    const int* __restrict__ sntcs, const float* __restrict__ W,
    float* __restrict__ out)
{
    extern __shared__ char smem[];
    uint32_t sb;
    asm("{ .reg .u64 t; cvta.to.shared.u64 t, %1; cvt.u32.u64 %0, t; }" : "=r"(sb) : "l"(smem));
    float*    sTab  = (float*)(smem + TAB_OFF);
    uint32_t* sMeta = (uint32_t*)(smem + META_OFF);

    const int tid  = threadIdx.x;
    const int lane = tid & 31;
    const int wg   = tid >> 5;               // warp owns words wg*4..wg*4+3
    const int wbase = blockIdx.x * NW_BLK;

    // ---- prologue: chars for this warp's 4 words (overlap with fill LDGs) ----
    int ch[4];
    #pragma unroll
    for (int t = 0; t < 4; t++)
        ch[t] = sntcs[(size_t)(wbase + wg * 4 + t) * LW + lane];

    // ---- fill fp32 table, conflict-free: thread = (char, dim-quarter) ----
    // LDG coalesced over chars; STS.128 covers banks 4c+d..+3 -> all 32 (CF).
    {
        const int fc = tid & 63;             // char row
        const int fq = tid >> 6;             // dim quarter (0..3)
        #pragma unroll
        for (int i = 0; i < 16; i++) {
            const int d0 = fq * 64 + i * 4;
            float4 v;
            v.x = W[(d0 + 0) * NC + fc];
            v.y = W[(d0 + 1) * NC + fc];
            v.z = W[(d0 + 2) * NC + fc];
            v.w = W[(d0 + 3) * NC + fc];
            *(float4*)(sTab + fc * TABROW + d0) = v;
        }
    }

    // ---- metadata + counts (warp-local, 4 words) ----
    #pragma unroll
    for (int t = 0; t < 4; t++) {
        int c = ch[t];
        unsigned key = ((unsigned)c << 5) | (unsigned)(31 - lane);
        #pragma unroll
        for (int off = 16; off; off >>= 1) {
            unsigned o = __shfl_xor_sync(0xffffffffu, key, off);
            key = key > o ? key : o;
        }
        int p  = 31 - (int)(key & 31u);                 // first-occurrence argmax
        int wl = p - 1; if (wl < 0) wl = 0;             // relu(argmax-1)
        int ends = __shfl_sync(0xffffffffu, c, wl);     // gather BEFORE scatter
        int s = (lane == wl) ? 0 : c;                   // scatter 0 at wl
        if (lane == 31) s = ends;                       // last := ends
        int fc2 = __shfl_sync(0xffffffffu, s, 0);       // first char (post-edit)
        int cnt0 = 0, cnt1 = 0;                         // counts, interior 1..30
        #pragma unroll
        for (int l = 1; l <= 30; l++) {
            int sl = __shfl_sync(0xffffffffu, s, l);
            cnt0 += (sl == lane);
            cnt1 += (sl == lane + 32);
        }
        const int w = wg * 4 + t;
        float f0 = (float)cnt0, f1 = (float)cnt1;
        asm volatile("st.shared.f32 [%0], %1;" ::
            "r"(sb + CNT_OFF + (uint32_t)(lane * CNTROW + w) * 4u), "f"(f0) : "memory");
        asm volatile("st.shared.f32 [%0], %1;" ::
            "r"(sb + CNT_OFF + (uint32_t)((lane + 32) * CNTROW + w) * 4u), "f"(f1) : "memory");
        if (lane == 0) {
            sMeta[w * 2]     = (uint32_t)fc2 * TABROWB;
            sMeta[w * 2 + 1] = (uint32_t)ends * TABROWB;
        }
    }
    __syncthreads();

    // ---- GEMM: bow[w][d] = sum_c cnt[w][c] * Wt[c][d] (f32x2) ----
    // thread tile: 4 words x 8 dims (lane*4..+3, 128+lane*4..+3)
    ull acc[4][4];
    #pragma unroll
    for (int w = 0; w < 4; w++)
        #pragma unroll
        for (int j = 0; j < 4; j++) acc[w][j] = 0ull;

    uint32_t tb = sb + TAB_OFF + (uint32_t)lane * 16u;
    uint32_t cb = sb + CNT_OFF + (uint32_t)wg * 16u;    // 4 f32 counts (16B)

    #pragma unroll 8
    for (int k = 0; k < NC; k++) {
        ull b0, b1, b2, b3, cr0, cr1;
        lds128(tb,        b0, b1);           // dims lane*4..+3      (CF)
        lds128(tb + 512u, b2, b3);           // dims 128+lane*4..+3  (CF)
        lds128(cb,        cr0, cr1);         // counts w0..w3 (broadcast)
        uint32_t c0, c1, c2, c3;
        asm("mov.b64 {%0,%1}, %2;" : "=r"(c0), "=r"(c1) : "l"(cr0));
        asm("mov.b64 {%0,%1}, %2;" : "=r"(c2), "=r"(c3) : "l"(cr1));
        ull p0 = pk(c0), p1 = pk(c1), p2 = pk(c2), p3 = pk(c3);
        fma2(acc[0][0], p0, b0); fma2(acc[0][1], p0, b1); fma2(acc[0][2], p0, b2); fma2(acc[0][3], p0, b3);
        fma2(acc[1][0], p1, b0); fma2(acc[1][1], p1, b1); fma2(acc[1][2], p1, b2); fma2(acc[1][3], p1, b3);
        fma2(acc[2][0], p2, b0); fma2(acc[2][1], p2, b1); fma2(acc[2][2], p2, b2); fma2(acc[2][3], p2, b3);
        fma2(acc[3][0], p3, b0); fma2(acc[3][1], p3, b1); fma2(acc[3][2], p3, b2); fma2(acc[3][3], p3, b3);
        tb += TABROWB;                        // 1040 B, stays 16B-aligned
        cb += CNTROW * 4u;                    // 144 B,  stays 16B-aligned
    }

    // ---- epilogue: bow stores + first/last gathers + pad ----
    #pragma unroll
    for (int w = 0; w < 4; w++) {
        const int gw = wbase + wg * 4 + w;
        float* o = out + (size_t)gw * OUTW;
        const int d4 = lane * 4;
        *(ull*)(o + 258 + d4)       = acc[w][0];   // bow (base 2+E3 = 258)
        *(ull*)(o + 260 + d4)       = acc[w][1];
        *(ull*)(o + 258 + 128 + d4) = acc[w][2];
        *(ull*)(o + 260 + 128 + d4) = acc[w][3];
        const uint32_t fo = sMeta[(wg * 4 + w) * 2];
        const uint32_t lo = sMeta[(wg * 4 + w) * 2 + 1];
        const uint32_t la = (uint32_t)lane * 16u;
        ull x, y;
        lds128(sb + TAB_OFF + fo + la, x, y);           // first
        *(ull*)(o + 2 + d4)   = x;  *(ull*)(o + 4 + d4)   = y;
        lds128(sb + TAB_OFF + fo + 512u + la, x, y);
        *(ull*)(o + 130 + d4) = x;  *(ull*)(o + 132 + d4) = y;
        lds128(sb + TAB_OFF + lo + la, x, y);           // last
        *(ull*)(o + 514 + d4) = x;  *(ull*)(o + 516 + d4) = y;
        lds128(sb + TAB_OFF + lo + 512u + la, x, y);
        *(ull*)(o + 642 + d4) = x;  *(ull*)(o + 644 + d4) = y;
        if (lane == 0) *(ull*)o = 0ull;                 // left zero pad
    }
}

extern "C" void kernel_launch(void* const* d_in, const int* in_sizes, int n_in,
                              void* d_out, int out_size)
{
    const int*   sntcs = (const int*)d_in[0];
    const float* W     = (const float*)d_in[1];
    float*       out   = (float*)d_out;

    cudaFuncSetAttribute(opb_kernel, cudaFuncAttributeMaxDynamicSharedMemorySize, SMEM_TOTAL);
    opb_kernel<<<GRID, BLOCKT, SMEM_TOTAL>>>(sntcs, W, out);
}